// round 1
// baseline (speedup 1.0000x reference)
#include <cuda_runtime.h>
#include <math.h>

// ---------------- problem constants ----------------
#define IMW   256
#define HWIMG 65536          // 256*256
#define BDIM  2
#define CDIM  96
#define C6    576            // 6*DIM
#define C2    192            // 2*DIM
#define CHID  255            // hidden_features
#define CHID2 510            // 2*hidden
#define HEADS 4
#define CH    48             // channels per head (192/4)
#define NF    33             // rfft bins of 64

// ---------------- scratch (static device memory; allocation-free) ----------------
__device__ float g_ln [(size_t)BDIM * CDIM  * HWIMG];
__device__ float g_h1 [(size_t)BDIM * C6    * HWIMG];
__device__ float g_h2 [(size_t)BDIM * C6    * HWIMG];
__device__ float g_att[(size_t)BDIM * C2    * HWIMG];
__device__ float g_x1 [(size_t)BDIM * CDIM  * HWIMG];
__device__ float g_f1 [(size_t)BDIM * CHID2 * HWIMG];
__device__ float g_f2 [(size_t)BDIM * CHID2 * HWIMG];
__device__ float g_g  [(size_t)BDIM * CHID  * HWIMG];

// ---------------- BiasFree LayerNorm (var over C, no mean subtraction in output) ----------------
__global__ void ln_kernel(const float* __restrict__ x, const float* __restrict__ w,
                          float* __restrict__ out) {
    int pix = blockIdx.x * 256 + threadIdx.x;     // 0..HWIMG-1
    int b   = blockIdx.y;
    const float* xb = x   + (size_t)b * CDIM * HWIMG + pix;
    float*       ob = out + (size_t)b * CDIM * HWIMG + pix;
    float s = 0.f, s2 = 0.f;
    #pragma unroll 8
    for (int c = 0; c < CDIM; c++) {
        float v = xb[(size_t)c * HWIMG];
        s += v; s2 += v * v;
    }
    float mean = s * (1.0f / CDIM);
    float var  = s2 * (1.0f / CDIM) - mean * mean;
    float inv  = rsqrtf(var + 1e-5f);
    #pragma unroll 8
    for (int c = 0; c < CDIM; c++) {
        ob[(size_t)c * HWIMG] = xb[(size_t)c * HWIMG] * inv * w[c];
    }
}

// ---------------- conv1x1 as SGEMM: Y[b][m][pix] = sum_k A[m][k] X[b][k][pix] (+R) ----------------
// 64x64 tile, BK=16, 256 threads, 4x4 per thread.
template<bool RESID>
__global__ void gemm_kernel(const float* __restrict__ A, const float* __restrict__ X,
                            const float* __restrict__ R, float* __restrict__ Y,
                            int M, int K) {
    __shared__ float As[16][64];   // As[k][m]
    __shared__ float Bs[16][64];   // Bs[k][n]
    int tid = threadIdx.x;
    int bn  = blockIdx.x * 64;
    int bm  = blockIdx.y * 64;
    int b   = blockIdx.z;
    const float* Xb = X + (size_t)b * K * HWIMG;

    int arow = tid >> 2, acolb = (tid & 3) * 4;
    int brow = tid >> 4, bcol  = (tid & 15) * 4;
    int ty   = tid >> 4, tx    = tid & 15;

    float acc[4][4];
    #pragma unroll
    for (int i = 0; i < 4; i++)
        #pragma unroll
        for (int j = 0; j < 4; j++) acc[i][j] = 0.f;

    for (int k0 = 0; k0 < K; k0 += 16) {
        #pragma unroll
        for (int i = 0; i < 4; i++) {
            int m = bm + arow, kk = k0 + acolb + i;
            As[acolb + i][arow] = (m < M && kk < K) ? A[(size_t)m * K + kk] : 0.f;
        }
        {
            int kk = k0 + brow;
            float4 bv = make_float4(0.f, 0.f, 0.f, 0.f);
            if (kk < K) bv = *(const float4*)(Xb + (size_t)kk * HWIMG + bn + bcol);
            *(float4*)&Bs[brow][bcol] = bv;
        }
        __syncthreads();
        #pragma unroll
        for (int k = 0; k < 16; k++) {
            float4 av = *(float4*)&As[k][ty * 4];
            float4 bv = *(float4*)&Bs[k][tx * 4];
            float aa[4] = {av.x, av.y, av.z, av.w};
            float bb[4] = {bv.x, bv.y, bv.z, bv.w};
            #pragma unroll
            for (int i = 0; i < 4; i++)
                #pragma unroll
                for (int j = 0; j < 4; j++)
                    acc[i][j] += aa[i] * bb[j];
        }
        __syncthreads();
    }

    #pragma unroll
    for (int i = 0; i < 4; i++) {
        int m = bm + ty * 4 + i;
        if (m < M) {
            size_t off = ((size_t)b * M + m) * HWIMG + bn + tx * 4;
            float4 o = make_float4(acc[i][0], acc[i][1], acc[i][2], acc[i][3]);
            if (RESID) {
                float4 r = *(const float4*)(R + off);
                o.x += r.x; o.y += r.y; o.z += r.z; o.w += r.w;
            }
            *(float4*)(Y + off) = o;
        }
    }
}

// ---------------- depthwise 3x3, zero padding ----------------
__global__ void dwconv_kernel(const float* __restrict__ in, const float* __restrict__ w,
                              float* __restrict__ out, int C) {
    int pix = blockIdx.x * 256 + threadIdx.x;
    int c = blockIdx.y, b = blockIdx.z;
    int y = pix >> 8, xx = pix & 255;
    const float* ip = in + ((size_t)b * C + c) * HWIMG;
    const float* wp = w + c * 9;
    float s = 0.f;
    #pragma unroll
    for (int dy = -1; dy <= 1; dy++) {
        int yy = y + dy;
        if (yy < 0 || yy > 255) continue;
        #pragma unroll
        for (int dx = -1; dx <= 1; dx++) {
            int x2 = xx + dx;
            if (x2 < 0 || x2 > 255) continue;
            s += ip[yy * IMW + x2] * wp[(dy + 1) * 3 + (dx + 1)];
        }
    }
    out[((size_t)b * C + c) * HWIMG + pix] = s;
}

// ---------------- windowed FFT attention: one block per (b, head, window) ----------------
// smem layout (floats):
//  sx: 48x65  @0        fr/fi q,k,v: 48x33 each @3120..
//  attn re/im: 33x33    norms: 33    cos/sin tab: 64+64
#define SM_SX   0
#define SM_QR   3120
#define SM_QI   4704
#define SM_KR   6288
#define SM_KI   7872
#define SM_VR   9456
#define SM_VI   11040
#define SM_AR   12624
#define SM_AI   13713
#define SM_NRM  14802
#define SM_TC   14835
#define SM_TS   14899
#define ATTN_SMEM_FLOATS 14963

__global__ void attn_kernel(const float* __restrict__ qkv, const float* __restrict__ temp,
                            float* __restrict__ outp) {
    extern __shared__ float sm[];
    float* sx  = sm + SM_SX;
    float* atr = sm + SM_AR;
    float* ati = sm + SM_AI;
    float* nrmv = sm + SM_NRM;
    float* tc  = sm + SM_TC;
    float* ts  = sm + SM_TS;

    int tid  = threadIdx.x;
    int wy   = blockIdx.x >> 5, wx = blockIdx.x & 31;
    int head = blockIdx.y, b = blockIdx.z;

    if (tid < 64) {
        float s, c;
        sincosf(6.2831853071795864f * (float)tid / 64.f, &s, &c);
        tc[tid] = c; ts[tid] = s;
    }

    size_t base = ((size_t)b * C6 + head * CH) * HWIMG + (size_t)(wy * 8) * IMW + wx * 8;

    // ---- rDFT of q, k, v windows ----
    for (int t = 0; t < 3; t++) {
        const float* src = qkv + base + (size_t)t * C2 * HWIMG;
        __syncthreads();  // protect sx (prev tensor) + tab on first iter
        for (int i = tid; i < CH * 64; i += 256) {
            int c = i >> 6, n = i & 63;
            sx[c * 65 + n] = src[(size_t)c * HWIMG + (n >> 3) * IMW + (n & 7)];
        }
        __syncthreads();
        if (tid < 204) {
            int c0 = (tid / 17) * 4, f0 = (tid % 17) * 2;
            float r0[4] = {0,0,0,0}, i0[4] = {0,0,0,0};
            float r1[4] = {0,0,0,0}, i1[4] = {0,0,0,0};
            int idx0 = 0, idx1 = 0;
            for (int n = 0; n < 64; n++) {
                float c0v = tc[idx0], s0v = ts[idx0];
                float c1v = tc[idx1], s1v = ts[idx1];
                #pragma unroll
                for (int j = 0; j < 4; j++) {
                    float xv = sx[(c0 + j) * 65 + n];
                    r0[j] += xv * c0v; i0[j] -= xv * s0v;
                    r1[j] += xv * c1v; i1[j] -= xv * s1v;
                }
                idx0 = (idx0 + f0) & 63;
                idx1 = (idx1 + f0 + 1) & 63;
            }
            float* R = sm + (t == 0 ? SM_QR : (t == 1 ? SM_KR : SM_VR));
            float* I = sm + (t == 0 ? SM_QI : (t == 1 ? SM_KI : SM_VI));
            #pragma unroll
            for (int j = 0; j < 4; j++) {
                R[(c0 + j) * NF + f0] = r0[j]; I[(c0 + j) * NF + f0] = i0[j];
                if (f0 + 1 < NF) { R[(c0 + j) * NF + f0 + 1] = r1[j]; I[(c0 + j) * NF + f0 + 1] = i1[j]; }
            }
        }
    }
    __syncthreads();

    float tv = temp[head];
    float* qr = sm + SM_QR; float* qi = sm + SM_QI;
    float* kr = sm + SM_KR; float* ki = sm + SM_KI;
    float* vr = sm + SM_VR; float* vi = sm + SM_VI;

    // ---- attn[f][g] = sum_c qf[c][f] * kf[c][g]  (complex, no conj) ----
    for (int e = tid; e < NF * NF; e += 256) {
        int f = e / NF, g = e - f * NF;
        float ar = 0.f, ai = 0.f;
        #pragma unroll 4
        for (int c = 0; c < CH; c++) {
            float a = qr[c * NF + f], bq = qi[c * NF + f];
            float cc = kr[c * NF + g], d = ki[c * NF + g];
            ar += a * cc - bq * d;
            ai += a * d + bq * cc;
        }
        atr[e] = ar * tv; ati[e] = ai * tv;
    }
    __syncthreads();

    // ---- row norms over g ----
    if (tid < NF) {
        float s = 0.f;
        #pragma unroll
        for (int g = 0; g < NF; g++) {
            float a = atr[tid * NF + g], bq = ati[tid * NF + g];
            s += a * a + bq * bq;
        }
        nrmv[tid] = rsqrtf(s);
    }
    __syncthreads();
    for (int e = tid; e < NF * NF; e += 256) {
        int f = e / NF;
        atr[e] *= nrmv[f]; ati[e] *= nrmv[f];
    }
    __syncthreads();

    // ---- of[c][f] = sum_g attn[f][g] * vf[c][g]  (write into qr/qi, now free) ----
    for (int e = tid; e < 24 * 17; e += 256) {
        int c0 = (e / 17) * 2, f0 = (e % 17) * 2;
        int f1 = (f0 + 1 < NF) ? f0 + 1 : f0;
        float r00 = 0, i00 = 0, r01 = 0, i01 = 0, r10 = 0, i10 = 0, r11 = 0, i11 = 0;
        #pragma unroll 3
        for (int g = 0; g < NF; g++) {
            float a0r = atr[f0 * NF + g], a0i = ati[f0 * NF + g];
            float a1r = atr[f1 * NF + g], a1i = ati[f1 * NF + g];
            float v0r = vr[c0 * NF + g], v0i = vi[c0 * NF + g];
            float v1r = vr[(c0 + 1) * NF + g], v1i = vi[(c0 + 1) * NF + g];
            r00 += a0r * v0r - a0i * v0i; i00 += a0r * v0i + a0i * v0r;
            r01 += a1r * v0r - a1i * v0i; i01 += a1r * v0i + a1i * v0r;
            r10 += a0r * v1r - a0i * v1i; i10 += a0r * v1i + a0i * v1r;
            r11 += a1r * v1r - a1i * v1i; i11 += a1r * v1i + a1i * v1r;
        }
        qr[c0 * NF + f0] = r00;  qi[c0 * NF + f0] = i00;
        qr[(c0 + 1) * NF + f0] = r10;  qi[(c0 + 1) * NF + f0] = i10;
        if (f0 + 1 < NF) {
            qr[c0 * NF + f0 + 1] = r01;  qi[c0 * NF + f0 + 1] = i01;
            qr[(c0 + 1) * NF + f0 + 1] = r11;  qi[(c0 + 1) * NF + f0 + 1] = i11;
        }
    }
    __syncthreads();

    // ---- irDFT (length 64 from 33 hermitian bins) + store ----
    float* outBase = outp + ((size_t)b * C2 + head * CH) * HWIMG + (size_t)(wy * 8) * IMW + wx * 8;
    for (int e = tid; e < 24 * 16; e += 256) {
        int c0 = (e / 16) * 2, n0 = (e % 16) * 4;
        float a0[4] = {0,0,0,0}, a1[4] = {0,0,0,0};
        for (int f = 0; f < NF; f++) {
            float wf = (f == 0 || f == 32) ? 1.f : 2.f;
            float p0r = qr[c0 * NF + f] * wf, p0i = qi[c0 * NF + f] * wf;
            float p1r = qr[(c0 + 1) * NF + f] * wf, p1i = qi[(c0 + 1) * NF + f] * wf;
            int idx = (f * n0) & 63;
            #pragma unroll
            for (int j = 0; j < 4; j++) {
                float cv = tc[idx], sv = ts[idx];
                a0[j] += p0r * cv - p0i * sv;
                a1[j] += p1r * cv - p1i * sv;
                idx = (idx + f) & 63;
            }
        }
        #pragma unroll
        for (int j = 0; j < 4; j++) {
            int n = n0 + j;
            size_t poff = (size_t)(n >> 3) * IMW + (n & 7);
            outBase[(size_t)c0 * HWIMG + poff]       = a0[j] * (1.f / 64.f);
            outBase[(size_t)(c0 + 1) * HWIMG + poff] = a1[j] * (1.f / 64.f);
        }
    }
}

// ---------------- GELU(x1) * x2 gate ----------------
__global__ void gate_kernel(const float* __restrict__ t, float* __restrict__ g) {
    size_t idx = (size_t)blockIdx.x * 256 + threadIdx.x;
    size_t total = (size_t)BDIM * CHID * HWIMG;
    if (idx >= total) return;
    size_t b = idx / ((size_t)CHID * HWIMG);
    size_t rem = idx - b * (size_t)CHID * HWIMG;
    size_t c = rem / HWIMG;
    size_t pix = rem - c * HWIMG;
    float v1 = t[((size_t)b * CHID2 + c) * HWIMG + pix];
    float v2 = t[((size_t)b * CHID2 + CHID + c) * HWIMG + pix];
    float ge = 0.5f * v1 * (1.f + erff(v1 * 0.70710678118654752f));
    g[idx] = ge * v2;
}

// ---------------- launch ----------------
extern "C" void kernel_launch(void* const* d_in, const int* in_sizes, int n_in,
                              void* d_out, int out_size) {
    const float* x      = (const float*)d_in[0];
    const float* w_hid  = (const float*)d_in[1];
    const float* w_hdw  = (const float*)d_in[2];
    const float* w_proj = (const float*)d_in[3];
    const float* temp   = (const float*)d_in[4];
    const float* n1w    = (const float*)d_in[5];
    const float* n2w    = (const float*)d_in[6];
    const float* w_fin  = (const float*)d_in[7];
    const float* w_fdw  = (const float*)d_in[8];
    const float* w_fout = (const float*)d_in[9];
    float* out = (float*)d_out;

    float *ln, *h1, *h2, *att, *x1, *f1, *f2, *gg;
    cudaGetSymbolAddress((void**)&ln,  g_ln);
    cudaGetSymbolAddress((void**)&h1,  g_h1);
    cudaGetSymbolAddress((void**)&h2,  g_h2);
    cudaGetSymbolAddress((void**)&att, g_att);
    cudaGetSymbolAddress((void**)&x1,  g_x1);
    cudaGetSymbolAddress((void**)&f1,  g_f1);
    cudaGetSymbolAddress((void**)&f2,  g_f2);
    cudaGetSymbolAddress((void**)&gg,  g_g);

    cudaFuncSetAttribute(attn_kernel, cudaFuncAttributeMaxDynamicSharedMemorySize,
                         ATTN_SMEM_FLOATS * 4);

    // 1) LN1
    ln_kernel<<<dim3(256, BDIM), 256>>>(x, n1w, ln);
    // 2) to_hidden 1x1 (96 -> 576)
    gemm_kernel<false><<<dim3(1024, 9, BDIM), 256>>>(w_hid, ln, nullptr, h1, C6, CDIM);
    // 3) dwconv 3x3 on 576 ch
    dwconv_kernel<<<dim3(256, C6, BDIM), 256>>>(h1, w_hdw, h2, C6);
    // 4) windowed FFT attention (8x8 windows, 4 heads)
    attn_kernel<<<dim3(1024, HEADS, BDIM), 256, ATTN_SMEM_FLOATS * 4>>>(h2, temp, att);
    // 5) project_out 1x1 (192 -> 96) + residual x
    gemm_kernel<true><<<dim3(1024, 2, BDIM), 256>>>(w_proj, att, x, x1, CDIM, C2);
    // 6) LN2
    ln_kernel<<<dim3(256, BDIM), 256>>>(x1, n2w, ln);
    // 7) ffn in 1x1 (96 -> 510)
    gemm_kernel<false><<<dim3(1024, 8, BDIM), 256>>>(w_fin, ln, nullptr, f1, CHID2, CDIM);
    // 8) dwconv 3x3 on 510 ch
    dwconv_kernel<<<dim3(256, CHID2, BDIM), 256>>>(f1, w_fdw, f2, CHID2);
    // 9) gelu gate
    {
        size_t total = (size_t)BDIM * CHID * HWIMG;
        gate_kernel<<<(unsigned)((total + 255) / 256), 256>>>(f2, gg);
    }
    // 10) ffn out 1x1 (255 -> 96) + residual x1  -> d_out
    gemm_kernel<true><<<dim3(1024, 2, BDIM), 256>>>(w_fout, gg, x1, out, CDIM, CHID);
}